// round 11
// baseline (speedup 1.0000x reference)
#include <cuda_runtime.h>

#define HH 1025
#define WW 1024
#define NIMG 4
#define RAD 15
#define KW 31

// scratch for harmonic (time-direction) medians
__device__ float g_harm[NIMG * HH * WW];

__device__ __forceinline__ void cas_asc(float &x, float &y) {
    float lo = fminf(x, y);
    float hi = fmaxf(x, y);
    x = lo; y = hi;
}

// arithmetic min/max on the fma pipe (FADD/FMUL), <=1ulp error — offloads
// the saturated alu pipe. Inputs are finite, non-negative here.
__device__ __forceinline__ float amax(float x, float y) {
    return 0.5f * ((x + y) + fabsf(x - y));
}
__device__ __forceinline__ float amin(float x, float y) {
    return 0.5f * ((x + y) - fabsf(x - y));
}

// bitonic sort of 32 floats ascending (a[31] is +INF sentinel)
__device__ __forceinline__ void sort32(float a[32]) {
#pragma unroll
    for (int k = 2; k <= 32; k <<= 1)
#pragma unroll
        for (int j = k >> 1; j > 0; j >>= 1)
#pragma unroll
            for (int i = 0; i < 32; ++i) {
                int l = i ^ j;
                if (l > i) {
                    if ((i & k) == 0) cas_asc(a[i], a[l]);
                    else              cas_asc(a[l], a[i]);
                }
            }
}

// sorted window a[0..30]; remove vold (present within ulp), insert vnew.
// delete: c[i] = (a[i] < vold) ? a[i] : a[i+1]
// insert: r[i] = max(c[i-1], min(c[i], vnew))
// ~1/3 of the insert ops use the fma-pipe arithmetic form to balance pipes.
__device__ __forceinline__ void slide31(float a[32], float vold, float vnew) {
    float c_prev = (a[0] < vold) ? a[0] : a[1];
    a[0] = fminf(c_prev, vnew);
#pragma unroll
    for (int i = 1; i <= 29; ++i) {
        float ci = (a[i] < vold) ? a[i] : a[i + 1];
        float ri;
        if (i % 5 < 2) ri = amax(c_prev, amin(ci, vnew));   // fma pipe
        else           ri = fmaxf(c_prev, fminf(ci, vnew)); // alu pipe
        a[i] = ri;
        c_prev = ci;
    }
    a[30] = fmaxf(c_prev, vnew);
}

// ───────────────────────── kernel A: harmonic (median along W) ─────────────
// 64-thread blocks, 64 rows x 16 output cols, smem 12KB -> 18 blocks/SM
#define A_ROWS 64
#define A_COLS 16
#define A_TW (A_COLS + 2 * RAD)  // 46
#define A_STR 47                 // odd -> conflict-free

__global__ __launch_bounds__(A_ROWS)
void hpss_harm(const float* __restrict__ S) {
    __shared__ float sm[A_ROWS * A_STR];
    const int img = blockIdx.z;
    const int h0 = blockIdx.y * A_ROWS;
    const int w0 = blockIdx.x * A_COLS;
    const float* __restrict__ Simg = S + (size_t)img * HH * WW;
    const int tid = threadIdx.x;

    for (int idx = tid; idx < A_ROWS * A_TW; idx += A_ROWS) {
        int r = idx / A_TW, c = idx - r * A_TW;
        int gh = h0 + r, gw = w0 - RAD + c;
        float v = 0.0f;
        if (gh < HH && gw >= 0 && gw < WW) v = Simg[gh * WW + gw];
        sm[r * A_STR + c] = v;
    }
    __syncthreads();

    if (h0 + tid < HH) {
        float* row = &sm[tid * A_STR];
        float a[32];
#pragma unroll
        for (int i = 0; i < 31; ++i) a[i] = row[i];
        a[31] = __int_as_float(0x7f800000);  // +INF
        sort32(a);
#pragma unroll 2
        for (int j = 0; j < A_COLS - 1; ++j) {
            float m = a[15];
            float vold = row[j];
            float vnew = row[j + KW];
            row[j] = m;            // slot j is dead for later windows
            slide31(a, vold, vnew);
        }
        row[A_COLS - 1] = a[15];
    }
    __syncthreads();

    float* __restrict__ Himg = g_harm + (size_t)img * HH * WW;
    for (int idx = tid; idx < A_ROWS * A_COLS; idx += A_ROWS) {
        int r = idx >> 4, c = idx & 15;
        int gh = h0 + r;
        if (gh < HH) Himg[gh * WW + w0 + c] = sm[r * A_STR + c];
    }
}

// ─────────── kernel B: percussive (median along H) + masks ─────────────────
// 128 threads, 128 cols x 16 output rows. Stage only the 31 rows
// [h0-15, h0+15] (init window + vold + sv) = 15.9KB -> 14 blocks/SM = 56
// warps, grid 2080 = exactly one wave. vnew rows stream from global with
// one-iteration prefetch.
#define PJ 16
#define B_ROWS 31   // staged rows
#define B_STR 31    // odd -> conflict-free (31 coprime with 32)

__global__ __launch_bounds__(128)
void hpss_perc(const float* __restrict__ S, float* __restrict__ out, int n) {
    __shared__ float sm[128 * B_STR];
    const int img = blockIdx.z;
    const int h0  = blockIdx.y * PJ;
    const int w0  = blockIdx.x * 128;
    const int tid = threadIdx.x;
    const float* __restrict__ Simg = S + (size_t)img * HH * WW;

    // stage rows [h0-15, h0+15] of cols [w0, w0+128), transposed, zero-padded
    for (int idx = tid; idx < B_ROWS * 128; idx += 128) {
        int r = idx >> 7, c = idx & 127;             // coalesced over c
        int gh = h0 - RAD + r;
        float v = 0.0f;
        if (gh >= 0 && gh < HH) v = Simg[(size_t)gh * WW + w0 + c];
        sm[c * B_STR + r] = v;
    }
    __syncthreads();

    const int w = w0 + tid;
    const float* __restrict__ colS = Simg + w;
    const float* __restrict__ colH = g_harm + (size_t)img * HH * WW + w;
    float* __restrict__ outH = out + (size_t)img * HH * WW + w;
    float* __restrict__ outP = outH + (size_t)n;
    const float* col = &sm[tid * B_STR];

    float a[32];
#pragma unroll
    for (int i = 0; i < 31; ++i) a[i] = col[i];
    a[31] = __int_as_float(0x7f800000);
    sort32(a);

    float harm = colH[(size_t)h0 * WW];                                  // j=0
    float vnew = (h0 + RAD + 1 < HH) ? colS[(size_t)(h0 + RAD + 1) * WW] : 0.0f;

#pragma unroll 2
    for (int j = 0; j < PJ; ++j) {
        const int hh = h0 + j;
        if (hh >= HH) break;             // uniform across block
        const float perc = a[15];
        const float sv   = col[j + RAD]; // S[hh][w] via LDS

        const float h2 = harm * harm, p2 = perc * perc;
        const float inv = __fdividef(1.0f, h2 + p2);
        outH[(size_t)hh * WW] = sv * (h2 * inv);
        outP[(size_t)hh * WW] = sv * (p2 * inv);

        if (j != PJ - 1) {
            // prefetch next iteration's globals before the slide
            const float harm_n = (hh + 1 < HH) ? colH[(size_t)(hh + 1) * WW] : 0.0f;
            const int hn = hh + RAD + 2;
            const float vnew_n = (hn < HH) ? colS[(size_t)hn * WW] : 0.0f;
            slide31(a, col[j], vnew);    // vold = row hh-15 via LDS
            harm = harm_n;
            vnew = vnew_n;
        }
    }
}

extern "C" void kernel_launch(void* const* d_in, const int* in_sizes, int n_in,
                              void* d_out, int out_size) {
    const float* S = (const float*)d_in[0];
    float* out = (float*)d_out;
    const int n = in_sizes[0];  // 4,198,400

    dim3 gA(WW / A_COLS, (HH + A_ROWS - 1) / A_ROWS, NIMG);  // 64 x 17 x 4
    hpss_harm<<<gA, A_ROWS>>>(S);
    dim3 gB(WW / 128, (HH + PJ - 1) / PJ, NIMG);             // 8 x 65 x 4
    hpss_perc<<<gB, 128>>>(S, out, n);

    (void)n_in; (void)out_size;
}

// round 12
// speedup vs baseline: 1.5489x; 1.5489x over previous
#include <cuda_runtime.h>
#include <cuda_fp16.h>
#include <string.h>

#define HH 1025
#define WW 1024
#define WP (WW / 2)   // float2 pairs per row
#define NIMG 4
#define RAD 15
#define KW 31

// scratch for harmonic medians (f32); aligned for float2 access
__device__ __align__(16) float g_harm[NIMG * HH * WW];

// ---- bit-cast helpers ----
__device__ __forceinline__ unsigned h2u(__half2 h) { unsigned u; memcpy(&u, &h, 4); return u; }
__device__ __forceinline__ __half2 u2h(unsigned u) { __half2 h; memcpy(&h, &u, 4); return h; }

// exact per-half select: mask m = 0xFFFF per true half
__device__ __forceinline__ __half2 hsel(__half2 a, __half2 b, unsigned m) {
    return u2h((h2u(a) & m) | (h2u(b) & ~m));   // single LOP3
}

__device__ __forceinline__ void cas2(__half2 &x, __half2 &y) {
    __half2 lo = __hmin2(x, y);
    __half2 hi = __hmax2(x, y);
    x = lo; y = hi;
}

// bitonic sort of 32 packed lanes, per-half independent, ascending
__device__ __forceinline__ void sort32h(__half2 a[32]) {
#pragma unroll
    for (int k = 2; k <= 32; k <<= 1)
#pragma unroll
        for (int j = k >> 1; j > 0; j >>= 1)
#pragma unroll
            for (int i = 0; i < 32; ++i) {
                int l = i ^ j;
                if (l > i) {
                    if ((i & k) == 0) cas2(a[i], a[l]);
                    else              cas2(a[l], a[i]);
                }
            }
}

// sorted packed window a[0..30] (per half); remove vold (bitwise present per
// half), insert vnew. All ops are exact bit-selections — no fp16 arithmetic.
__device__ __forceinline__ void slide31h(__half2 a[32], __half2 vold, __half2 vnew) {
    unsigned m0 = __hlt2_mask(a[0], vold);
    __half2 c_prev = hsel(a[0], a[1], m0);
    a[0] = __hmin2(c_prev, vnew);
#pragma unroll
    for (int i = 1; i <= 29; ++i) {
        unsigned mi = __hlt2_mask(a[i], vold);
        __half2 ci = hsel(a[i], a[i + 1], mi);
        a[i] = __hmax2(c_prev, __hmin2(ci, vnew));
        c_prev = ci;
    }
    a[30] = __hmax2(c_prev, vnew);
}

// ───────────── kernel A: harmonic (median along W), row-pairs packed ───────
#define AR 128            // tile rows = 64 packed pairs
#define AC 16             // output cols per block
#define ATW (AC + 2*RAD)  // 46
#define ASTR 47           // odd stride -> conflict-free

__global__ __launch_bounds__(64)
void hpss_harm(const float* __restrict__ S) {
    __shared__ unsigned sm[64 * ASTR];   // packed (row2r, row2r+1) tile, 12KB
    const int img = blockIdx.z;
    const int h0 = blockIdx.y * AR;
    const int w0 = blockIdx.x * AC;
    const float* __restrict__ Simg = S + (size_t)img * HH * WW;
    const int tid = threadIdx.x;

    for (int idx = tid; idx < 64 * ATW; idx += 64) {
        int r = idx / ATW, c = idx - r * ATW;
        int gh = h0 + 2 * r, gw = w0 - RAD + c;
        float v0 = 0.f, v1 = 0.f;
        if (gw >= 0 && gw < WW) {
            if (gh < HH)     v0 = Simg[(size_t)gh * WW + gw];
            if (gh + 1 < HH) v1 = Simg[(size_t)(gh + 1) * WW + gw];
        }
        sm[r * ASTR + c] = h2u(__floats2half2_rn(v0, v1));
    }
    __syncthreads();

    if (h0 + 2 * tid < HH) {
        unsigned* row = &sm[tid * ASTR];
        __half2 a[32];
#pragma unroll
        for (int i = 0; i < 31; ++i) a[i] = u2h(row[i]);
        a[31] = u2h(0x7C007C00u);   // +INF per half
        sort32h(a);
#pragma unroll 2
        for (int j = 0; j < AC - 1; ++j) {
            __half2 vold = u2h(row[j]);
            __half2 vnew = u2h(row[j + KW]);
            row[j] = h2u(a[15]);    // write median into dead slot
            slide31h(a, vold, vnew);
        }
        row[AC - 1] = h2u(a[15]);
    }
    __syncthreads();

    float* __restrict__ Himg = g_harm + (size_t)img * HH * WW;
    for (int idx = tid; idx < AR * AC; idx += 64) {
        int gr = idx >> 4, c = idx & 15;
        int gh = h0 + gr;
        if (gh < HH) {
            __half2 h = u2h(sm[(gr >> 1) * ASTR + c]);
            Himg[(size_t)gh * WW + w0 + c] = (gr & 1) ? __high2float(h) : __low2float(h);
        }
    }
}

// ──────── kernel B: percussive (median along H) + masks, col-pairs packed ──
#define PPJ 16   // outputs per thread along H

__global__ __launch_bounds__(128)
void hpss_perc(const float* __restrict__ S, float* __restrict__ out, int n) {
    const int img = blockIdx.z;
    const int h0  = blockIdx.y * PPJ;
    const int wp  = blockIdx.x * 128 + threadIdx.x;   // float2 pair index
    const float2* __restrict__ cs = (const float2*)(S + (size_t)img * HH * WW) + wp;
    const float2* __restrict__ ch = (const float2*)(g_harm + (size_t)img * HH * WW) + wp;
    float2* __restrict__ oh = (float2*)(out + (size_t)img * HH * WW) + wp;
    float2* __restrict__ op = (float2*)(out + (size_t)n + (size_t)img * HH * WW) + wp;

    __half2 a[32];
#pragma unroll
    for (int i = 0; i < 31; ++i) {
        int gh = h0 - RAD + i;
        float2 v = make_float2(0.f, 0.f);
        if (gh >= 0 && gh < HH) v = cs[(size_t)gh * WP];
        a[i] = __floats2half2_rn(v.x, v.y);
    }
    a[31] = u2h(0x7C007C00u);
    sort32h(a);

#pragma unroll 2
    for (int j = 0; j < PPJ; ++j) {
        const int hh = h0 + j;
        if (hh >= HH) break;            // uniform across block

        // issue all loads first (independent of the window state)
        const float2 sv = cs[(size_t)hh * WP];
        const float2 hm = ch[(size_t)hh * WP];
        const int ho = hh - RAD, hn = hh + RAD + 1;
        float2 vo = make_float2(0.f, 0.f), vn = make_float2(0.f, 0.f);
        if (ho >= 0)  vo = cs[(size_t)ho * WP];
        if (hn < HH)  vn = cs[(size_t)hn * WP];

        const float px = __low2float(a[15]);
        const float py = __high2float(a[15]);

        // POWER=2, MARGIN=1 -> masks = h2/(h2+p2), p2/(h2+p2) (fp32 math)
        const float h2x = hm.x * hm.x, p2x = px * px;
        const float h2y = hm.y * hm.y, p2y = py * py;
        const float ix = __fdividef(1.0f, h2x + p2x);
        const float iy = __fdividef(1.0f, h2y + p2y);
        oh[(size_t)hh * WP] = make_float2(sv.x * (h2x * ix), sv.y * (h2y * iy));
        op[(size_t)hh * WP] = make_float2(sv.x * (p2x * ix), sv.y * (p2y * iy));

        if (j != PPJ - 1)
            slide31h(a, __floats2half2_rn(vo.x, vo.y), __floats2half2_rn(vn.x, vn.y));
    }
}

extern "C" void kernel_launch(void* const* d_in, const int* in_sizes, int n_in,
                              void* d_out, int out_size) {
    const float* S = (const float*)d_in[0];
    float* out = (float*)d_out;
    const int n = in_sizes[0];  // 4,198,400

    dim3 gA(WW / AC, (HH + AR - 1) / AR, NIMG);    // 64 x 9 x 4
    hpss_harm<<<gA, 64>>>(S);
    dim3 gB(WP / 128, (HH + PPJ - 1) / PPJ, NIMG); // 4 x 65 x 4
    hpss_perc<<<gB, 128>>>(S, out, n);

    (void)n_in; (void)out_size;
}

// round 13
// speedup vs baseline: 1.9031x; 1.2287x over previous
#include <cuda_runtime.h>
#include <cuda_fp16.h>
#include <string.h>

#define HH 1025
#define WW 1024
#define WP (WW / 2)   // float2 pairs per row
#define NIMG 4
#define RAD 15
#define KW 31

// scratch for harmonic medians (f32); aligned for float2 access
__device__ __align__(16) float g_harm[NIMG * HH * WW];

// ---- bit-cast helpers ----
__device__ __forceinline__ unsigned h2u(__half2 h) { unsigned u; memcpy(&u, &h, 4); return u; }
__device__ __forceinline__ __half2 u2h(unsigned u) { __half2 h; memcpy(&h, &u, 4); return h; }

// exact per-half select: mask m = 0xFFFF per true half
__device__ __forceinline__ __half2 hsel(__half2 a, __half2 b, unsigned m) {
    return u2h((h2u(a) & m) | (h2u(b) & ~m));   // single LOP3
}

__device__ __forceinline__ void cas2(__half2 &x, __half2 &y) {
    __half2 lo = __hmin2(x, y);
    __half2 hi = __hmax2(x, y);
    x = lo; y = hi;
}

// bitonic sort of 32 packed lanes, per-half independent, ascending
__device__ __forceinline__ void sort32h(__half2 a[32]) {
#pragma unroll
    for (int k = 2; k <= 32; k <<= 1)
#pragma unroll
        for (int j = k >> 1; j > 0; j >>= 1)
#pragma unroll
            for (int i = 0; i < 32; ++i) {
                int l = i ^ j;
                if (l > i) {
                    if ((i & k) == 0) cas2(a[i], a[l]);
                    else              cas2(a[l], a[i]);
                }
            }
}

// sorted packed window a[0..30] (per half); remove vold (bitwise present per
// half), insert vnew. All ops are exact bit-selections — no fp16 arithmetic.
__device__ __forceinline__ void slide31h(__half2 a[32], __half2 vold, __half2 vnew) {
    unsigned m0 = __hlt2_mask(a[0], vold);
    __half2 c_prev = hsel(a[0], a[1], m0);
    a[0] = __hmin2(c_prev, vnew);
#pragma unroll
    for (int i = 1; i <= 29; ++i) {
        unsigned mi = __hlt2_mask(a[i], vold);
        __half2 ci = hsel(a[i], a[i + 1], mi);
        a[i] = __hmax2(c_prev, __hmin2(ci, vnew));
        c_prev = ci;
    }
    a[30] = __hmax2(c_prev, vnew);
}

// ───────────── kernel A: harmonic (median along W), row-pairs packed ───────
#define AR 128            // tile rows = 64 packed pairs
#define AC 8              // output cols per block
#define ATW (AC + 2*RAD)  // 38
#define ASTR 39           // odd stride -> conflict-free

__global__ __launch_bounds__(64)
void hpss_harm(const float* __restrict__ S) {
    __shared__ unsigned sm[64 * ASTR];   // packed (row2r, row2r+1) tile, ~10KB
    const int img = blockIdx.z;
    const int h0 = blockIdx.y * AR;
    const int w0 = blockIdx.x * AC;
    const float* __restrict__ Simg = S + (size_t)img * HH * WW;
    const int tid = threadIdx.x;

    for (int idx = tid; idx < 64 * ATW; idx += 64) {
        int r = idx / ATW, c = idx - r * ATW;
        int gh = h0 + 2 * r, gw = w0 - RAD + c;
        float v0 = 0.f, v1 = 0.f;
        if (gw >= 0 && gw < WW) {
            if (gh < HH)     v0 = Simg[(size_t)gh * WW + gw];
            if (gh + 1 < HH) v1 = Simg[(size_t)(gh + 1) * WW + gw];
        }
        sm[r * ASTR + c] = h2u(__floats2half2_rn(v0, v1));
    }
    __syncthreads();

    if (h0 + 2 * tid < HH) {
        unsigned* row = &sm[tid * ASTR];
        __half2 a[32];
#pragma unroll
        for (int i = 0; i < 31; ++i) a[i] = u2h(row[i]);
        a[31] = u2h(0x7C007C00u);   // +INF per half
        sort32h(a);
#pragma unroll
        for (int j = 0; j < AC - 1; ++j) {
            __half2 vold = u2h(row[j]);
            __half2 vnew = u2h(row[j + KW]);
            row[j] = h2u(a[15]);    // write median into dead slot
            slide31h(a, vold, vnew);
        }
        row[AC - 1] = h2u(a[15]);
    }
    __syncthreads();

    float* __restrict__ Himg = g_harm + (size_t)img * HH * WW;
    for (int idx = tid; idx < AR * AC; idx += 64) {
        int gr = idx >> 3, c = idx & 7;
        int gh = h0 + gr;
        if (gh < HH) {
            __half2 h = u2h(sm[(gr >> 1) * ASTR + c]);
            Himg[(size_t)gh * WW + w0 + c] = (gr & 1) ? __high2float(h) : __low2float(h);
        }
    }
}

// ──────── kernel B: percussive (median along H) + masks, col-pairs packed ──
#define PPJ 8   // outputs per thread along H

__global__ __launch_bounds__(128)
void hpss_perc(const float* __restrict__ S, float* __restrict__ out, int n) {
    const int img = blockIdx.z;
    const int h0  = blockIdx.y * PPJ;
    const int wp  = blockIdx.x * 128 + threadIdx.x;   // float2 pair index
    const float2* __restrict__ cs = (const float2*)(S + (size_t)img * HH * WW) + wp;
    const float2* __restrict__ ch = (const float2*)(g_harm + (size_t)img * HH * WW) + wp;
    float2* __restrict__ oh = (float2*)(out + (size_t)img * HH * WW) + wp;
    float2* __restrict__ op = (float2*)(out + (size_t)n + (size_t)img * HH * WW) + wp;

    __half2 a[32];
#pragma unroll
    for (int i = 0; i < 31; ++i) {
        int gh = h0 - RAD + i;
        float2 v = make_float2(0.f, 0.f);
        if (gh >= 0 && gh < HH) v = cs[(size_t)gh * WP];
        a[i] = __floats2half2_rn(v.x, v.y);
    }
    a[31] = u2h(0x7C007C00u);
    sort32h(a);

#pragma unroll
    for (int j = 0; j < PPJ; ++j) {
        const int hh = h0 + j;
        if (hh >= HH) break;            // uniform across block

        // issue all loads first (independent of the window state)
        const float2 sv = cs[(size_t)hh * WP];
        const float2 hm = ch[(size_t)hh * WP];
        const int ho = hh - RAD, hn = hh + RAD + 1;
        float2 vo = make_float2(0.f, 0.f), vn = make_float2(0.f, 0.f);
        if (ho >= 0)  vo = cs[(size_t)ho * WP];
        if (hn < HH)  vn = cs[(size_t)hn * WP];

        const float px = __low2float(a[15]);
        const float py = __high2float(a[15]);

        // POWER=2, MARGIN=1 -> masks = h2/(h2+p2), p2/(h2+p2) (fp32 math)
        const float h2x = hm.x * hm.x, p2x = px * px;
        const float h2y = hm.y * hm.y, p2y = py * py;
        const float ix = __fdividef(1.0f, h2x + p2x);
        const float iy = __fdividef(1.0f, h2y + p2y);
        oh[(size_t)hh * WP] = make_float2(sv.x * (h2x * ix), sv.y * (h2y * iy));
        op[(size_t)hh * WP] = make_float2(sv.x * (p2x * ix), sv.y * (p2y * iy));

        if (j != PPJ - 1)
            slide31h(a, __floats2half2_rn(vo.x, vo.y), __floats2half2_rn(vn.x, vn.y));
    }
}

extern "C" void kernel_launch(void* const* d_in, const int* in_sizes, int n_in,
                              void* d_out, int out_size) {
    const float* S = (const float*)d_in[0];
    float* out = (float*)d_out;
    const int n = in_sizes[0];  // 4,198,400

    dim3 gA(WW / AC, (HH + AR - 1) / AR, NIMG);    // 128 x 9 x 4
    hpss_harm<<<gA, 64>>>(S);
    dim3 gB(WP / 128, (HH + PPJ - 1) / PPJ, NIMG); // 4 x 129 x 4
    hpss_perc<<<gB, 128>>>(S, out, n);

    (void)n_in; (void)out_size;
}

// round 16
// speedup vs baseline: 2.0703x; 1.0878x over previous
#include <cuda_runtime.h>
#include <cuda_fp16.h>
#include <string.h>

#define HH 1025
#define WW 1024
#define WP (WW / 2)     // float2 pairs per row
#define NPAIR 513       // row pairs (HH odd -> last pair half-valid)
#define NIMG 4
#define RAD 15
#define KW 31

// scratch for harmonic medians: packed half2 (row 2p in low, row 2p+1 in high)
__device__ __align__(16) unsigned g_harm2[NIMG * NPAIR * WW];

// ---- bit-cast helpers ----
__device__ __forceinline__ unsigned h2u(__half2 h) { unsigned u; memcpy(&u, &h, 4); return u; }
__device__ __forceinline__ __half2 u2h(unsigned u) { __half2 h; memcpy(&h, &u, 4); return h; }

// exact per-half select: mask m = 0xFFFF per true half
__device__ __forceinline__ __half2 hsel(__half2 a, __half2 b, unsigned m) {
    return u2h((h2u(a) & m) | (h2u(b) & ~m));   // single LOP3
}

__device__ __forceinline__ void cas2(__half2 &x, __half2 &y) {
    __half2 lo = __hmin2(x, y);
    __half2 hi = __hmax2(x, y);
    x = lo; y = hi;
}

// ── Batcher odd-even mergesort, 32 lanes, per-half independent (191 CAS) ──
template<int LO, int N, int R>
__device__ __forceinline__ void oem_merge(__half2 a[32]) {
    constexpr int M = R * 2;
    if constexpr (M < N) {
        oem_merge<LO, N, M>(a);
        oem_merge<LO + R, N, M>(a);
#pragma unroll
        for (int i = LO + R; i + R < LO + N; i += M) cas2(a[i], a[i + R]);
    } else {
        cas2(a[LO], a[LO + R]);
    }
}
template<int LO, int N>
__device__ __forceinline__ void oem_sort(__half2 a[32]) {
    if constexpr (N > 1) {
        constexpr int M = N / 2;
        oem_sort<LO, M>(a);
        oem_sort<LO + M, M>(a);
        oem_merge<LO, N, 1>(a);
    }
}

// sorted packed window a[0..30] (per half); remove vold, insert vnew.
__device__ __forceinline__ void slide31h(__half2 a[32], __half2 vold, __half2 vnew) {
    unsigned m0 = __hlt2_mask(a[0], vold);
    __half2 c_prev = hsel(a[0], a[1], m0);
    a[0] = __hmin2(c_prev, vnew);
#pragma unroll
    for (int i = 1; i <= 29; ++i) {
        unsigned mi = __hlt2_mask(a[i], vold);
        __half2 ci = hsel(a[i], a[i + 1], mi);
        a[i] = __hmax2(c_prev, __hmin2(ci, vnew));
        c_prev = ci;
    }
    a[30] = __hmax2(c_prev, vnew);
}

// ───────────── kernel A: harmonic (median along W), row-pairs packed ───────
#define AR 128            // tile rows = 64 packed pairs
#define AC 8              // output cols per block
#define ATW (AC + 2*RAD)  // 38
#define ASTR 39           // odd stride -> conflict-free

__global__ __launch_bounds__(64)
void hpss_harm(const float* __restrict__ S) {
    __shared__ unsigned sm[64 * ASTR];   // packed (row 2r, 2r+1) tile, ~10KB
    const int img = blockIdx.z;
    const int h0 = blockIdx.y * AR;
    const int w0 = blockIdx.x * AC;
    const float* __restrict__ Simg = S + (size_t)img * HH * WW;
    const int tid = threadIdx.x;

    for (int idx = tid; idx < 64 * ATW; idx += 64) {
        int r = idx / ATW, c = idx - r * ATW;
        int gh = h0 + 2 * r, gw = w0 - RAD + c;
        float v0 = 0.f, v1 = 0.f;
        if (gw >= 0 && gw < WW) {
            if (gh < HH)     v0 = Simg[(size_t)gh * WW + gw];
            if (gh + 1 < HH) v1 = Simg[(size_t)(gh + 1) * WW + gw];
        }
        sm[r * ASTR + c] = h2u(__floats2half2_rn(v0, v1));
    }
    __syncthreads();

    if (h0 + 2 * tid < HH) {
        unsigned* row = &sm[tid * ASTR];
        __half2 a[32];
#pragma unroll
        for (int i = 0; i < 31; ++i) a[i] = u2h(row[i]);
        a[31] = u2h(0x7C007C00u);   // +INF per half
        oem_sort<0, 32>(a);
#pragma unroll
        for (int j = 0; j < AC - 1; ++j) {
            __half2 vold = u2h(row[j]);
            __half2 vnew = u2h(row[j + KW]);
            row[j] = h2u(a[15]);    // write median into dead slot
            slide31h(a, vold, vnew);
        }
        row[AC - 1] = h2u(a[15]);
    }
    __syncthreads();

    // writeback: raw packed words, no conversion
    unsigned* __restrict__ H2 = g_harm2 + (size_t)img * NPAIR * WW;
    const int p0 = h0 >> 1;
    for (int idx = tid; idx < 64 * AC; idx += 64) {
        int pr = idx >> 3, c = idx & 7;
        if (p0 + pr < NPAIR)
            H2[(size_t)(p0 + pr) * WW + w0 + c] = sm[pr * ASTR + c];
    }
}

// ──────── kernel B: percussive (median along H) + masks, col-pairs packed ──
#define PPJ 8   // outputs per thread along H

__global__ __launch_bounds__(128)
void hpss_perc(const float* __restrict__ S, float* __restrict__ out, int n) {
    const int img = blockIdx.z;
    const int h0  = blockIdx.y * PPJ;
    const int wp  = blockIdx.x * 128 + threadIdx.x;   // float2 pair index
    const float2*   __restrict__ cs  = (const float2*)(S + (size_t)img * HH * WW) + wp;
    const unsigned* __restrict__ gh2 = g_harm2 + (size_t)img * NPAIR * WW;
    float2* __restrict__ oh = (float2*)(out + (size_t)img * HH * WW) + wp;
    float2* __restrict__ op = (float2*)(out + (size_t)n + (size_t)img * HH * WW) + wp;

    __half2 a[32];
#pragma unroll
    for (int i = 0; i < 31; ++i) {
        int gh = h0 - RAD + i;
        float2 v = make_float2(0.f, 0.f);
        if (gh >= 0 && gh < HH) v = cs[(size_t)gh * WP];
        a[i] = __floats2half2_rn(v.x, v.y);
    }
    a[31] = u2h(0x7C007C00u);
    oem_sort<0, 32>(a);

#pragma unroll
    for (int j = 0; j < PPJ; ++j) {
        const int hh = h0 + j;
        if (hh >= HH) break;            // uniform across block

        // issue loads first (independent of window state)
        const float2 sv = cs[(size_t)hh * WP];
        const uint2 hw = *(const uint2*)(gh2 + (size_t)(hh >> 1) * WW + 2 * wp);
        const int ho = hh - RAD, hn = hh + RAD + 1;
        float2 vo = make_float2(0.f, 0.f), vn = make_float2(0.f, 0.f);
        if (ho >= 0)  vo = cs[(size_t)ho * WP];
        if (hn < HH)  vn = cs[(size_t)hn * WP];

        const unsigned sh = (hh & 1) << 4;   // lane select within the pair word
        const float hx = __half2float(__ushort_as_half((unsigned short)(hw.x >> sh)));
        const float hy = __half2float(__ushort_as_half((unsigned short)(hw.y >> sh)));
        const float px = __low2float(a[15]);
        const float py = __high2float(a[15]);

        // POWER=2, MARGIN=1 -> masks = h2/(h2+p2), p2/(h2+p2) (fp32 math)
        const float h2x = hx * hx, p2x = px * px;
        const float h2y = hy * hy, p2y = py * py;
        const float ix = __fdividef(1.0f, h2x + p2x);
        const float iy = __fdividef(1.0f, h2y + p2y);
        oh[(size_t)hh * WP] = make_float2(sv.x * (h2x * ix), sv.y * (h2y * iy));
        op[(size_t)hh * WP] = make_float2(sv.x * (p2x * ix), sv.y * (p2y * iy));

        if (j != PPJ - 1)
            slide31h(a, __floats2half2_rn(vo.x, vo.y), __floats2half2_rn(vn.x, vn.y));
    }
}

extern "C" void kernel_launch(void* const* d_in, const int* in_sizes, int n_in,
                              void* d_out, int out_size) {
    const float* S = (const float*)d_in[0];
    float* out = (float*)d_out;
    const int n = in_sizes[0];  // 4,198,400

    dim3 gA(WW / AC, (HH + AR - 1) / AR, NIMG);    // 128 x 9 x 4
    hpss_harm<<<gA, 64>>>(S);
    dim3 gB(WP / 128, (HH + PPJ - 1) / PPJ, NIMG); // 4 x 129 x 4
    hpss_perc<<<gB, 128>>>(S, out, n);

    (void)n_in; (void)out_size;
}